// round 9
// baseline (speedup 1.0000x reference)
#include <cuda_runtime.h>
#include <math.h>

#define POI   5000
#define EMB   256
#define UNITS 512
#define QDIM  256
#define BATCH 64
#define X1DIM  (EMB + QDIM)        // 512
#define CATDIM (EMB + 2 * UNITS)   // 1280
#define NCH    10                  // context p-chunks (5000/10 = 500)
#define UHALF  256                 // attention u-half size

// ---------------- scratch (no cudaMalloc allowed) ----------------
__device__ float g_h[BATCH * UNITS];
__device__ float g_qproj[BATCH * UNITS];
__device__ float g_vproj[POI * UNITS];            // 10.24 MB
__device__ float g_score[BATCH * POI];
__device__ float g_ctxpart[NCH * BATCH * EMB];
__device__ float g_outcat[BATCH * CATDIM];
__device__ float g_part[10 * BATCH * POI];        // partial slabs (12.8 MB max: fc S=10)

__device__ __forceinline__ float tanh_ap(float x) {
    float y;
    asm("tanh.approx.f32 %0, %1;" : "=f"(y) : "f"(x));
    return y;
}

// ---------------- gemm_v2: C[M,N] = A[M,K] @ W[K,N] (+bias iff gridDim.z==1) -----
template <int BM, int BN, int TM, int TN>
__global__ void gemm_v2_kernel(const float* __restrict__ A,
                               const float* __restrict__ W,
                               const float* __restrict__ bias,
                               float* __restrict__ out,
                               int M, int N, int K, int kchunk) {
    __shared__ float As[32][BM + 1];   // As[k][m]
    __shared__ float Ws[32][BN];       // Ws[k][n]
    const int tid = threadIdx.x;
    const int r = tid >> 4;
    const int c = tid & 15;
    const int n0 = blockIdx.x * BN;
    const int m0 = blockIdx.y * BM;
    const int kbase = blockIdx.z * kchunk;

    float acc[TM][TN];
#pragma unroll
    for (int i = 0; i < TM; i++)
#pragma unroll
        for (int j = 0; j < TN; j++) acc[i][j] = 0.f;

    for (int kk = kbase; kk < kbase + kchunk; kk += 32) {
#pragma unroll
        for (int pass = 0; pass < (BM * 32) / 1024; pass++) {
            int idx = pass * 1024 + tid * 4;
            int m = idx >> 5;
            int k = idx & 31;
            float4 v = make_float4(0.f, 0.f, 0.f, 0.f);
            if (m0 + m < M) v = *(const float4*)(A + (size_t)(m0 + m) * K + kk + k);
            As[k + 0][m] = v.x;
            As[k + 1][m] = v.y;
            As[k + 2][m] = v.z;
            As[k + 3][m] = v.w;
        }
#pragma unroll
        for (int pass = 0; pass < (32 * BN) / 1024; pass++) {
            int idx = pass * 1024 + tid * 4;
            int k = idx / BN;
            int n = idx % BN;
            float4 v = make_float4(0.f, 0.f, 0.f, 0.f);
            if (n0 + n < N) v = *(const float4*)(W + (size_t)(kk + k) * N + n0 + n);
            *(float4*)&Ws[k][n] = v;
        }
        __syncthreads();
#pragma unroll
        for (int k = 0; k < 32; k++) {
            float a[TM];
#pragma unroll
            for (int i = 0; i < TM; i++) a[i] = As[k][r * TM + i];
            float b[TN];
#pragma unroll
            for (int j = 0; j < TN; j += 4)
                *(float4*)&b[j] = *(const float4*)&Ws[k][c * TN + j];
#pragma unroll
            for (int i = 0; i < TM; i++)
#pragma unroll
                for (int j = 0; j < TN; j++)
                    acc[i][j] = fmaf(a[i], b[j], acc[i][j]);
        }
        __syncthreads();
    }

    const bool direct = (gridDim.z == 1);
    float* dst = direct ? out : out + (size_t)blockIdx.z * M * N;
#pragma unroll
    for (int i = 0; i < TM; i++) {
        int m = m0 + r * TM + i;
        if (m >= M) continue;
#pragma unroll
        for (int j = 0; j < TN; j += 4) {
            int n = n0 + c * TN + j;
            if (n < N) {
                float4 v;
                v.x = acc[i][j + 0] + (direct ? bias[n + 0] : 0.f);
                v.y = acc[i][j + 1] + (direct ? bias[n + 1] : 0.f);
                v.z = acc[i][j + 2] + (direct ? bias[n + 2] : 0.f);
                v.w = acc[i][j + 3] + (direct ? bias[n + 3] : 0.f);
                *(float4*)(dst + (size_t)m * N + n) = v;
            }
        }
    }
}

// ---------------- merged GRU matmuls: slabs 0..7 = xm (x1 built inline), 8..15 = hm
__global__ void gru_mm_kernel(const int* __restrict__ x,
                              const float* __restrict__ query,
                              const float* __restrict__ emb,
                              const float* __restrict__ dec_hidden,
                              const float* __restrict__ Wk,
                              const float* __restrict__ Wr,
                              float* __restrict__ part) {
    const int NN = 3 * UNITS;
    __shared__ float As[32][65];
    __shared__ float Ws[32][64];
    const int tid = threadIdx.x;
    const int r = tid >> 4;
    const int c = tid & 15;
    const int n0 = blockIdx.x * 64;
    const bool isX = blockIdx.z < 8;
    const int kbase = (isX ? blockIdx.z : blockIdx.z - 8) * 64;
    const float* W = isX ? Wk : Wr;

    float acc[4][4];
#pragma unroll
    for (int i = 0; i < 4; i++)
#pragma unroll
        for (int j = 0; j < 4; j++) acc[i][j] = 0.f;

    for (int kk = kbase; kk < kbase + 64; kk += 32) {
#pragma unroll
        for (int pass = 0; pass < 2; pass++) {
            int idx = pass * 1024 + tid * 4;
            int m = idx >> 5;
            int k = idx & 31;
            int gk = kk + k;
            float4 v;
            if (isX) {
                if (gk < EMB)
                    v = *(const float4*)(emb + (size_t)x[m] * EMB + gk);
                else
                    v = *(const float4*)(query + (size_t)m * QDIM + gk - EMB);
            } else {
                v = *(const float4*)(dec_hidden + (size_t)m * UNITS + gk);
            }
            As[k + 0][m] = v.x;
            As[k + 1][m] = v.y;
            As[k + 2][m] = v.z;
            As[k + 3][m] = v.w;
        }
#pragma unroll
        for (int pass = 0; pass < 2; pass++) {
            int idx = pass * 1024 + tid * 4;
            int k = idx >> 6;
            int n = idx & 63;
            *(float4*)&Ws[k][n] = *(const float4*)(W + (size_t)(kk + k) * NN + n0 + n);
        }
        __syncthreads();
#pragma unroll
        for (int k = 0; k < 32; k++) {
            float a0 = As[k][r * 4 + 0];
            float a1 = As[k][r * 4 + 1];
            float a2 = As[k][r * 4 + 2];
            float a3 = As[k][r * 4 + 3];
            float4 b = *(const float4*)&Ws[k][c * 4];
            acc[0][0] = fmaf(a0, b.x, acc[0][0]); acc[0][1] = fmaf(a0, b.y, acc[0][1]);
            acc[0][2] = fmaf(a0, b.z, acc[0][2]); acc[0][3] = fmaf(a0, b.w, acc[0][3]);
            acc[1][0] = fmaf(a1, b.x, acc[1][0]); acc[1][1] = fmaf(a1, b.y, acc[1][1]);
            acc[1][2] = fmaf(a1, b.z, acc[1][2]); acc[1][3] = fmaf(a1, b.w, acc[1][3]);
            acc[2][0] = fmaf(a2, b.x, acc[2][0]); acc[2][1] = fmaf(a2, b.y, acc[2][1]);
            acc[2][2] = fmaf(a2, b.z, acc[2][2]); acc[2][3] = fmaf(a2, b.w, acc[2][3]);
            acc[3][0] = fmaf(a3, b.x, acc[3][0]); acc[3][1] = fmaf(a3, b.y, acc[3][1]);
            acc[3][2] = fmaf(a3, b.z, acc[3][2]); acc[3][3] = fmaf(a3, b.w, acc[3][3]);
        }
        __syncthreads();
    }

    float* dst = part + (size_t)blockIdx.z * BATCH * NN;
#pragma unroll
    for (int i = 0; i < 4; i++) {
        int m = r * 4 + i;
        int n = n0 + c * 4;
        float4 v = make_float4(acc[i][0], acc[i][1], acc[i][2], acc[i][3]);
        *(float4*)(dst + (size_t)m * NN + n) = v;
    }
}

// ---------------- reduce K-split partials + bias ----------------
__global__ void reduce_bias_kernel(const float* __restrict__ part,
                                   const float* __restrict__ bias,
                                   float* __restrict__ C,
                                   int MN, int N, int S) {
    int i = blockIdx.x * 256 + threadIdx.x;
    if (i >= MN) return;
    float s = 0.f;
    for (int z = 0; z < S; z++) s += part[(size_t)z * MN + i];
    C[i] = s + bias[i % N];
}

// ---------------- GRU gates: sums 8 xm slabs + 8 hm slabs + bias ----------------
__global__ void gru_gates_kernel(const float* __restrict__ part,
                                 const float* __restrict__ bias,
                                 const float* __restrict__ h_in,
                                 float* __restrict__ h_scratch,
                                 float* __restrict__ out_state,
                                 float* __restrict__ out_output) {
    const int NN = 3 * UNITS;
    int b = blockIdx.x;
    int u = threadIdx.x;               // 512
    float xz = bias[u], xr = bias[UNITS + u], xh = bias[2 * UNITS + u];
    float hz = bias[NN + u], hr = bias[NN + UNITS + u], hh = bias[NN + 2 * UNITS + u];
#pragma unroll
    for (int z = 0; z < 8; z++) {
        const float* px = part + (size_t)z * BATCH * NN + b * NN;
        const float* ph = part + (size_t)(8 + z) * BATCH * NN + b * NN;
        xz += px[u]; xr += px[UNITS + u]; xh += px[2 * UNITS + u];
        hz += ph[u]; hr += ph[UNITS + u]; hh += ph[2 * UNITS + u];
    }
    float z = 1.f / (1.f + expf(-(xz + hz)));
    float r = 1.f / (1.f + expf(-(xr + hr)));
    float hc = tanhf(xh + r * hh);
    float h = h_in[b * UNITS + u];
    float hn = z * h + (1.f - z) * hc;
    h_scratch[b * UNITS + u] = hn;
    if (out_state)  out_state[b * UNITS + u] = hn;
    if (out_output) out_output[b * UNITS + u] = hn;
}

// ---------------- attention score over a u-half, 4 batch rows per block ---------
// grid (ceil(POI/128), BATCH/4), block 128. first!=0: score = acc + Vb.
// first==0: score += acc. u range = [ubase, ubase+UHALF).
__global__ void attn_score_half_kernel(const float* __restrict__ vproj,
                                       const float* __restrict__ qproj,
                                       const float* __restrict__ Vw,
                                       const float* __restrict__ Vb,
                                       float* __restrict__ score,
                                       int ubase, int first) {
    __shared__ float q_s[4][UHALF];    // 4 KB
    __shared__ float vw_s[UHALF];      // 1 KB
    __shared__ float v_s[128][33];     // 16.9 KB
    const int tid = threadIdx.x;       // 128
    const int p0 = blockIdx.x * 128;
    const int b0 = blockIdx.y * 4;

    for (int t = tid; t < 4 * UHALF; t += 128) {
        int b = t >> 8, u = t & (UHALF - 1);
        q_s[b][u] = qproj[(b0 + b) * UNITS + ubase + u];
    }
    for (int t = tid; t < UHALF; t += 128) vw_s[t] = Vw[ubase + t];

    float acc0 = 0.f, acc1 = 0.f, acc2 = 0.f, acc3 = 0.f;
    for (int u0 = 0; u0 < UHALF; u0 += 32) {
        __syncthreads();               // also covers q_s/vw_s on first iter
        for (int t = tid; t < 128 * 32; t += 128) {
            int p = t >> 5, j = t & 31;
            v_s[p][j] = (p0 + p < POI)
                        ? vproj[(size_t)(p0 + p) * UNITS + ubase + u0 + j] : 0.f;
        }
        __syncthreads();
#pragma unroll
        for (int j = 0; j < 32; ++j) {
            float v  = v_s[tid][j];
            float vw = vw_s[u0 + j];
            acc0 = fmaf(vw, tanh_ap(v + q_s[0][u0 + j]), acc0);
            acc1 = fmaf(vw, tanh_ap(v + q_s[1][u0 + j]), acc1);
            acc2 = fmaf(vw, tanh_ap(v + q_s[2][u0 + j]), acc2);
            acc3 = fmaf(vw, tanh_ap(v + q_s[3][u0 + j]), acc3);
        }
    }
    if (p0 + tid < POI) {
        if (first) {
            float vb = Vb[0];
            score[(size_t)(b0 + 0) * POI + p0 + tid] = acc0 + vb;
            score[(size_t)(b0 + 1) * POI + p0 + tid] = acc1 + vb;
            score[(size_t)(b0 + 2) * POI + p0 + tid] = acc2 + vb;
            score[(size_t)(b0 + 3) * POI + p0 + tid] = acc3 + vb;
        } else {
            score[(size_t)(b0 + 0) * POI + p0 + tid] += acc0;
            score[(size_t)(b0 + 1) * POI + p0 + tid] += acc1;
            score[(size_t)(b0 + 2) * POI + p0 + tid] += acc2;
            score[(size_t)(b0 + 3) * POI + p0 + tid] += acc3;
        }
    }
}

// ---------------- softmax over POI per batch row (in place) ----------------
__global__ void softmax_rows_kernel(float* __restrict__ score) {
    int b = blockIdx.x;
    int tid = threadIdx.x;             // 256
    __shared__ float red[256];
    float m = -1e30f;
    for (int p = tid; p < POI; p += 256) m = fmaxf(m, score[b * POI + p]);
    red[tid] = m;
    __syncthreads();
    for (int s = 128; s > 0; s >>= 1) {
        if (tid < s) red[tid] = fmaxf(red[tid], red[tid + s]);
        __syncthreads();
    }
    m = red[0];
    __syncthreads();
    float sum = 0.f;
    for (int p = tid; p < POI; p += 256) {
        float e = __expf(score[b * POI + p] - m);
        score[b * POI + p] = e;
        sum += e;
    }
    red[tid] = sum;
    __syncthreads();
    for (int s = 128; s > 0; s >>= 1) {
        if (tid < s) red[tid] += red[tid + s];
        __syncthreads();
    }
    float inv = 1.f / red[0];
    for (int p = tid; p < POI; p += 256) score[b * POI + p] *= inv;
}

// ---------------- context partials: 4 batch rows per block, NCH p-chunks --------
__global__ void context_partial_kernel(const float* __restrict__ attn,
                                       const float* __restrict__ emb,
                                       float* __restrict__ part) {
    const int PC = POI / NCH;          // 500
    int b0 = blockIdx.x * 4;
    int ch = blockIdx.y;
    int e  = threadIdx.x;              // 256 == EMB
    int p0 = ch * PC;
    const float* a0 = attn + (b0 + 0) * POI;
    const float* a1 = attn + (b0 + 1) * POI;
    const float* a2 = attn + (b0 + 2) * POI;
    const float* a3 = attn + (b0 + 3) * POI;
    float c0 = 0.f, c1 = 0.f, c2 = 0.f, c3 = 0.f;
#pragma unroll 4
    for (int p = p0; p < p0 + PC; ++p) {
        float ev = emb[p * EMB + e];
        c0 = fmaf(a0[p], ev, c0);
        c1 = fmaf(a1[p], ev, c1);
        c2 = fmaf(a2[p], ev, c2);
        c3 = fmaf(a3[p], ev, c3);
    }
    part[(ch * BATCH + b0 + 0) * EMB + e] = c0;
    part[(ch * BATCH + b0 + 1) * EMB + e] = c1;
    part[(ch * BATCH + b0 + 2) * EMB + e] = c2;
    part[(ch * BATCH + b0 + 3) * EMB + e] = c3;
}

// ---------------- outcat = [sum(ctx partials) | h | cat_dec] ----------------
__global__ void build_outcat_kernel(const float* __restrict__ part,
                                    const float* __restrict__ h,
                                    const float* __restrict__ cat_dec,
                                    float* __restrict__ outcat) {
    int b = blockIdx.x;
    int e = threadIdx.x;               // 256
    float s = 0.f;
#pragma unroll
    for (int ch = 0; ch < NCH; ch++) s += part[(ch * BATCH + b) * EMB + e];
    outcat[b * CATDIM + e] = s;
    for (int c = e; c < UNITS; c += 256) {
        outcat[b * CATDIM + EMB + c]         = h[b * UNITS + c];
        outcat[b * CATDIM + EMB + UNITS + c] = cat_dec[b * UNITS + c];
    }
}

// ---------------- launch ----------------
extern "C" void kernel_launch(void* const* d_in, const int* in_sizes, int n_in,
                              void* d_out, int out_size) {
    const int*   x          = (const int*)  d_in[0];
    const float* query      = (const float*)d_in[1];
    const float* emb        = (const float*)d_in[2];
    // d_in[3] = A_hat (unused)
    const float* dec_hidden = (const float*)d_in[4];
    const float* cat_dec    = (const float*)d_in[5];
    const float* gru_kernel = (const float*)d_in[6];
    const float* gru_rec    = (const float*)d_in[7];
    const float* gru_bias   = (const float*)d_in[8];
    const float* W1_w       = (const float*)d_in[9];
    const float* W1_b       = (const float*)d_in[10];
    const float* W2_w       = (const float*)d_in[11];
    const float* W2_b       = (const float*)d_in[12];
    const float* V_w        = (const float*)d_in[13];
    const float* V_b        = (const float*)d_in[14];
    const float* fc_w       = (const float*)d_in[15];
    const float* fc_b       = (const float*)d_in[16];

    float* out        = (float*)d_out;
    float* out_logits = out;
    float* out_state  = (out_size >= BATCH * POI + BATCH * UNITS)
                        ? out + BATCH * POI : nullptr;
    float* out_output = (out_size >= BATCH * POI + 2 * BATCH * UNITS)
                        ? out + BATCH * POI + BATCH * UNITS : nullptr;

    float *g_h_p, *g_qp_p, *g_vp_p, *g_sc_p, *g_cp_p, *g_oc_p, *g_pt_p;
    cudaGetSymbolAddress((void**)&g_h_p,  g_h);
    cudaGetSymbolAddress((void**)&g_qp_p, g_qproj);
    cudaGetSymbolAddress((void**)&g_vp_p, g_vproj);
    cudaGetSymbolAddress((void**)&g_sc_p, g_score);
    cudaGetSymbolAddress((void**)&g_cp_p, g_ctxpart);
    cudaGetSymbolAddress((void**)&g_oc_p, g_outcat);
    cudaGetSymbolAddress((void**)&g_pt_p, g_part);

    // One-time stream/event setup (created on the uncaptured correctness call,
    // reused on capture — identical launch topology every call).
    static cudaStream_t s2 = nullptr;
    static cudaEvent_t evFork = nullptr, evJ1 = nullptr, evJ2 = nullptr;
    if (!s2) {
        cudaStreamCreateWithFlags(&s2, cudaStreamNonBlocking);
        cudaEventCreateWithFlags(&evFork, cudaEventDisableTiming);
        cudaEventCreateWithFlags(&evJ1, cudaEventDisableTiming);
        cudaEventCreateWithFlags(&evJ2, cudaEventDisableTiming);
    }

    // ---- fork: vproj halves on s2 (overlap GRU chain, then attn pass 1) ----
    cudaEventRecord(evFork, 0);
    cudaStreamWaitEvent(s2, evFork, 0);

    // vproj half 1: columns [0, 256)
    gemm_v2_kernel<128, 64, 8, 4><<<dim3(UHALF / 64, (POI + 127) / 128, 1), 256, 0, s2>>>(
        emb, W1_w, W1_b, g_vp_p, POI, UNITS, EMB, EMB);
    cudaEventRecord(evJ1, s2);
    // vproj half 2: columns [256, 512) (pointer-offset; N=UNITS is the stride)
    gemm_v2_kernel<128, 64, 8, 4><<<dim3(UHALF / 64, (POI + 127) / 128, 1), 256, 0, s2>>>(
        emb, W1_w + UHALF, W1_b + UHALF, g_vp_p + UHALF, POI, UNITS, EMB, EMB);
    cudaEventRecord(evJ2, s2);

    // ---- GRU chain on main stream (concurrent with vproj half 1) ----
    gru_mm_kernel<<<dim3(3 * UNITS / 64, 1, 16), 256>>>(
        x, query, emb, dec_hidden, gru_kernel, gru_rec, g_pt_p);
    gru_gates_kernel<<<BATCH, UNITS>>>(g_pt_p, gru_bias, dec_hidden,
                                       g_h_p, out_state, out_output);
    gemm_v2_kernel<64, 64, 4, 4><<<dim3(UNITS / 64, 1, 8), 256>>>(
        g_h_p, W2_w, nullptr, g_pt_p, BATCH, UNITS, UNITS, 64);
    reduce_bias_kernel<<<(BATCH * UNITS + 255) / 256, 256>>>(
        g_pt_p, W2_b, g_qp_p, BATCH * UNITS, UNITS, 8);

    // ---- attn pass 1 (u 0..255) after vproj half 1; overlaps vproj half 2 ----
    cudaStreamWaitEvent(0, evJ1, 0);
    attn_score_half_kernel<<<dim3((POI + 127) / 128, BATCH / 4), 128>>>(
        g_vp_p, g_qp_p, V_w, V_b, g_sc_p, 0, 1);

    // ---- attn pass 2 (u 256..511) after vproj half 2 ----
    cudaStreamWaitEvent(0, evJ2, 0);
    attn_score_half_kernel<<<dim3((POI + 127) / 128, BATCH / 4), 128>>>(
        g_vp_p, g_qp_p, V_w, V_b, g_sc_p, UHALF, 0);

    softmax_rows_kernel<<<BATCH, 256>>>(g_sc_p);
    context_partial_kernel<<<dim3(BATCH / 4, NCH), 256>>>(g_sc_p, emb, g_cp_p);
    build_outcat_kernel<<<BATCH, 256>>>(g_cp_p, g_h_p, cat_dec, g_oc_p);

    // logits = outcat @ fc_w + fc_b : split 10
    gemm_v2_kernel<64, 128, 4, 8><<<dim3((POI + 127) / 128, 1, 10), 256>>>(
        g_oc_p, fc_w, nullptr, g_pt_p, BATCH, POI, CATDIM, 128);
    reduce_bias_kernel<<<(BATCH * POI + 255) / 256, 256>>>(
        g_pt_p, fc_b, out_logits, BATCH * POI, POI, 10);
}

// round 10
// speedup vs baseline: 1.1749x; 1.1749x over previous
#include <cuda_runtime.h>
#include <math.h>

#define POI   5000
#define EMB   256
#define UNITS 512
#define QDIM  256
#define BATCH 64
#define X1DIM  (EMB + QDIM)        // 512
#define NCH    10                  // context p-chunks (5000/10 = 500)

// ---------------- scratch (no cudaMalloc allowed; disjoint per concurrent use) --
__device__ float g_h[BATCH * UNITS];
__device__ float g_qproj[BATCH * UNITS];
__device__ float g_ctx[BATCH * EMB];
__device__ float g_vproj[POI * UNITS];                 // 10.24 MB
__device__ float g_score[BATCH * POI];
__device__ float g_ctxpart[NCH * BATCH * EMB];
__device__ float g_gru_part[16 * BATCH * 3 * UNITS];   // 6.3 MB
__device__ float g_qp_part[8 * BATCH * UNITS];         // 1.0 MB
__device__ float g_fc_part[10 * BATCH * POI];          // 12.8 MB

__device__ __forceinline__ float tanh_ap(float x) {
    float y;
    asm("tanh.approx.f32 %0, %1;" : "=f"(y) : "f"(x));
    return y;
}

// ---------------- gemm_v2: C[M,N] = A[M,K] @ W[K,N] (+bias iff gridDim.z==1) -----
// Partial mode (gridDim.z>1): slab z covers K rows [z*kchunk, (z+1)*kchunk).
template <int BM, int BN, int TM, int TN>
__global__ void gemm_v2_kernel(const float* __restrict__ A,
                               const float* __restrict__ W,
                               const float* __restrict__ bias,
                               float* __restrict__ out,
                               int M, int N, int K, int kchunk) {
    __shared__ float As[32][BM + 1];   // As[k][m]
    __shared__ float Ws[32][BN];       // Ws[k][n]
    const int tid = threadIdx.x;
    const int r = tid >> 4;
    const int c = tid & 15;
    const int n0 = blockIdx.x * BN;
    const int m0 = blockIdx.y * BM;
    const int kbase = blockIdx.z * kchunk;

    float acc[TM][TN];
#pragma unroll
    for (int i = 0; i < TM; i++)
#pragma unroll
        for (int j = 0; j < TN; j++) acc[i][j] = 0.f;

    for (int kk = kbase; kk < kbase + kchunk; kk += 32) {
#pragma unroll
        for (int pass = 0; pass < (BM * 32) / 1024; pass++) {
            int idx = pass * 1024 + tid * 4;
            int m = idx >> 5;
            int k = idx & 31;
            float4 v = make_float4(0.f, 0.f, 0.f, 0.f);
            if (m0 + m < M) v = *(const float4*)(A + (size_t)(m0 + m) * K + kk + k);
            As[k + 0][m] = v.x;
            As[k + 1][m] = v.y;
            As[k + 2][m] = v.z;
            As[k + 3][m] = v.w;
        }
#pragma unroll
        for (int pass = 0; pass < (32 * BN) / 1024; pass++) {
            int idx = pass * 1024 + tid * 4;
            int k = idx / BN;
            int n = idx % BN;
            float4 v = make_float4(0.f, 0.f, 0.f, 0.f);
            if (n0 + n < N) v = *(const float4*)(W + (size_t)(kk + k) * N + n0 + n);
            *(float4*)&Ws[k][n] = v;
        }
        __syncthreads();
#pragma unroll
        for (int k = 0; k < 32; k++) {
            float a[TM];
#pragma unroll
            for (int i = 0; i < TM; i++) a[i] = As[k][r * TM + i];
            float b[TN];
#pragma unroll
            for (int j = 0; j < TN; j += 4)
                *(float4*)&b[j] = *(const float4*)&Ws[k][c * TN + j];
#pragma unroll
            for (int i = 0; i < TM; i++)
#pragma unroll
                for (int j = 0; j < TN; j++)
                    acc[i][j] = fmaf(a[i], b[j], acc[i][j]);
        }
        __syncthreads();
    }

    const bool direct = (gridDim.z == 1);
    float* dst = direct ? out : out + (size_t)blockIdx.z * M * N;
#pragma unroll
    for (int i = 0; i < TM; i++) {
        int m = m0 + r * TM + i;
        if (m >= M) continue;
#pragma unroll
        for (int j = 0; j < TN; j += 4) {
            int n = n0 + c * TN + j;
            if (n < N) {
                float4 v;
                v.x = acc[i][j + 0] + (direct ? bias[n + 0] : 0.f);
                v.y = acc[i][j + 1] + (direct ? bias[n + 1] : 0.f);
                v.z = acc[i][j + 2] + (direct ? bias[n + 2] : 0.f);
                v.w = acc[i][j + 3] + (direct ? bias[n + 3] : 0.f);
                *(float4*)(dst + (size_t)m * N + n) = v;
            }
        }
    }
}

// ---------------- merged GRU matmuls: slabs 0..7 = xm (x1 built inline), 8..15 = hm
__global__ void gru_mm_kernel(const int* __restrict__ x,
                              const float* __restrict__ query,
                              const float* __restrict__ emb,
                              const float* __restrict__ dec_hidden,
                              const float* __restrict__ Wk,
                              const float* __restrict__ Wr,
                              float* __restrict__ part) {
    const int NN = 3 * UNITS;
    __shared__ float As[32][65];
    __shared__ float Ws[32][64];
    const int tid = threadIdx.x;
    const int r = tid >> 4;
    const int c = tid & 15;
    const int n0 = blockIdx.x * 64;
    const bool isX = blockIdx.z < 8;
    const int kbase = (isX ? blockIdx.z : blockIdx.z - 8) * 64;
    const float* W = isX ? Wk : Wr;

    float acc[4][4];
#pragma unroll
    for (int i = 0; i < 4; i++)
#pragma unroll
        for (int j = 0; j < 4; j++) acc[i][j] = 0.f;

    for (int kk = kbase; kk < kbase + 64; kk += 32) {
#pragma unroll
        for (int pass = 0; pass < 2; pass++) {
            int idx = pass * 1024 + tid * 4;
            int m = idx >> 5;
            int k = idx & 31;
            int gk = kk + k;
            float4 v;
            if (isX) {
                if (gk < EMB)
                    v = *(const float4*)(emb + (size_t)x[m] * EMB + gk);
                else
                    v = *(const float4*)(query + (size_t)m * QDIM + gk - EMB);
            } else {
                v = *(const float4*)(dec_hidden + (size_t)m * UNITS + gk);
            }
            As[k + 0][m] = v.x;
            As[k + 1][m] = v.y;
            As[k + 2][m] = v.z;
            As[k + 3][m] = v.w;
        }
#pragma unroll
        for (int pass = 0; pass < 2; pass++) {
            int idx = pass * 1024 + tid * 4;
            int k = idx >> 6;
            int n = idx & 63;
            *(float4*)&Ws[k][n] = *(const float4*)(W + (size_t)(kk + k) * NN + n0 + n);
        }
        __syncthreads();
#pragma unroll
        for (int k = 0; k < 32; k++) {
            float a0 = As[k][r * 4 + 0];
            float a1 = As[k][r * 4 + 1];
            float a2 = As[k][r * 4 + 2];
            float a3 = As[k][r * 4 + 3];
            float4 b = *(const float4*)&Ws[k][c * 4];
            acc[0][0] = fmaf(a0, b.x, acc[0][0]); acc[0][1] = fmaf(a0, b.y, acc[0][1]);
            acc[0][2] = fmaf(a0, b.z, acc[0][2]); acc[0][3] = fmaf(a0, b.w, acc[0][3]);
            acc[1][0] = fmaf(a1, b.x, acc[1][0]); acc[1][1] = fmaf(a1, b.y, acc[1][1]);
            acc[1][2] = fmaf(a1, b.z, acc[1][2]); acc[1][3] = fmaf(a1, b.w, acc[1][3]);
            acc[2][0] = fmaf(a2, b.x, acc[2][0]); acc[2][1] = fmaf(a2, b.y, acc[2][1]);
            acc[2][2] = fmaf(a2, b.z, acc[2][2]); acc[2][3] = fmaf(a2, b.w, acc[2][3]);
            acc[3][0] = fmaf(a3, b.x, acc[3][0]); acc[3][1] = fmaf(a3, b.y, acc[3][1]);
            acc[3][2] = fmaf(a3, b.z, acc[3][2]); acc[3][3] = fmaf(a3, b.w, acc[3][3]);
        }
        __syncthreads();
    }

    float* dst = part + (size_t)blockIdx.z * BATCH * NN;
#pragma unroll
    for (int i = 0; i < 4; i++) {
        int m = r * 4 + i;
        int n = n0 + c * 4;
        float4 v = make_float4(acc[i][0], acc[i][1], acc[i][2], acc[i][3]);
        *(float4*)(dst + (size_t)m * NN + n) = v;
    }
}

// ---------------- reduce K-split partials + bias ----------------
__global__ void reduce_bias_kernel(const float* __restrict__ part,
                                   const float* __restrict__ bias,
                                   float* __restrict__ C,
                                   int MN, int N, int S) {
    int i = blockIdx.x * 256 + threadIdx.x;
    if (i >= MN) return;
    float s = 0.f;
    for (int z = 0; z < S; z++) s += part[(size_t)z * MN + i];
    C[i] = s + bias[i % N];
}

// ---------------- GRU gates: sums 8 xm slabs + 8 hm slabs + bias ----------------
__global__ void gru_gates_kernel(const float* __restrict__ part,
                                 const float* __restrict__ bias,
                                 const float* __restrict__ h_in,
                                 float* __restrict__ h_scratch,
                                 float* __restrict__ out_state,
                                 float* __restrict__ out_output) {
    const int NN = 3 * UNITS;
    int b = blockIdx.x;
    int u = threadIdx.x;               // 512
    float xz = bias[u], xr = bias[UNITS + u], xh = bias[2 * UNITS + u];
    float hz = bias[NN + u], hr = bias[NN + UNITS + u], hh = bias[NN + 2 * UNITS + u];
#pragma unroll
    for (int z = 0; z < 8; z++) {
        const float* px = part + (size_t)z * BATCH * NN + b * NN;
        const float* ph = part + (size_t)(8 + z) * BATCH * NN + b * NN;
        xz += px[u]; xr += px[UNITS + u]; xh += px[2 * UNITS + u];
        hz += ph[u]; hr += ph[UNITS + u]; hh += ph[2 * UNITS + u];
    }
    float z = 1.f / (1.f + expf(-(xz + hz)));
    float r = 1.f / (1.f + expf(-(xr + hr)));
    float hc = tanhf(xh + r * hh);
    float h = h_in[b * UNITS + u];
    float hn = z * h + (1.f - z) * hc;
    h_scratch[b * UNITS + u] = hn;
    if (out_state)  out_state[b * UNITS + u] = hn;
    if (out_output) out_output[b * UNITS + u] = hn;
}

// ---------------- attention score, 4 batch rows per block (R6/R8-proven) --------
__global__ void attn_score_kernel(const float* __restrict__ vproj,
                                  const float* __restrict__ qproj,
                                  const float* __restrict__ Vw,
                                  const float* __restrict__ Vb,
                                  float* __restrict__ score) {
    __shared__ float q_s[4][UNITS];
    __shared__ float vw_s[UNITS];
    __shared__ float v_s[128][33];
    const int tid = threadIdx.x;       // 128
    const int p0 = blockIdx.x * 128;
    const int b0 = blockIdx.y * 4;

    for (int t = tid; t < 4 * UNITS; t += 128) {
        int b = t >> 9, u = t & 511;
        q_s[b][u] = qproj[(b0 + b) * UNITS + u];
    }
    for (int t = tid; t < UNITS; t += 128) vw_s[t] = Vw[t];

    float acc0 = 0.f, acc1 = 0.f, acc2 = 0.f, acc3 = 0.f;
    for (int u0 = 0; u0 < UNITS; u0 += 32) {
        __syncthreads();
        for (int t = tid; t < 128 * 32; t += 128) {
            int p = t >> 5, j = t & 31;
            v_s[p][j] = (p0 + p < POI) ? vproj[(size_t)(p0 + p) * UNITS + u0 + j] : 0.f;
        }
        __syncthreads();
#pragma unroll
        for (int j = 0; j < 32; ++j) {
            float v  = v_s[tid][j];
            float vw = vw_s[u0 + j];
            acc0 = fmaf(vw, tanh_ap(v + q_s[0][u0 + j]), acc0);
            acc1 = fmaf(vw, tanh_ap(v + q_s[1][u0 + j]), acc1);
            acc2 = fmaf(vw, tanh_ap(v + q_s[2][u0 + j]), acc2);
            acc3 = fmaf(vw, tanh_ap(v + q_s[3][u0 + j]), acc3);
        }
    }
    if (p0 + tid < POI) {
        float vb = Vb[0];
        score[(size_t)(b0 + 0) * POI + p0 + tid] = acc0 + vb;
        score[(size_t)(b0 + 1) * POI + p0 + tid] = acc1 + vb;
        score[(size_t)(b0 + 2) * POI + p0 + tid] = acc2 + vb;
        score[(size_t)(b0 + 3) * POI + p0 + tid] = acc3 + vb;
    }
}

// ---------------- softmax over POI per batch row (in place) ----------------
__global__ void softmax_rows_kernel(float* __restrict__ score) {
    int b = blockIdx.x;
    int tid = threadIdx.x;             // 256
    __shared__ float red[256];
    float m = -1e30f;
    for (int p = tid; p < POI; p += 256) m = fmaxf(m, score[b * POI + p]);
    red[tid] = m;
    __syncthreads();
    for (int s = 128; s > 0; s >>= 1) {
        if (tid < s) red[tid] = fmaxf(red[tid], red[tid + s]);
        __syncthreads();
    }
    m = red[0];
    __syncthreads();
    float sum = 0.f;
    for (int p = tid; p < POI; p += 256) {
        float e = __expf(score[b * POI + p] - m);
        score[b * POI + p] = e;
        sum += e;
    }
    red[tid] = sum;
    __syncthreads();
    for (int s = 128; s > 0; s >>= 1) {
        if (tid < s) red[tid] += red[tid + s];
        __syncthreads();
    }
    float inv = 1.f / red[0];
    for (int p = tid; p < POI; p += 256) score[b * POI + p] *= inv;
}

// ---------------- context partials: 4 batch rows per block, NCH p-chunks --------
__global__ void context_partial_kernel(const float* __restrict__ attn,
                                       const float* __restrict__ emb,
                                       float* __restrict__ part) {
    const int PC = POI / NCH;          // 500
    int b0 = blockIdx.x * 4;
    int ch = blockIdx.y;
    int e  = threadIdx.x;              // 256 == EMB
    int p0 = ch * PC;
    const float* a0 = attn + (b0 + 0) * POI;
    const float* a1 = attn + (b0 + 1) * POI;
    const float* a2 = attn + (b0 + 2) * POI;
    const float* a3 = attn + (b0 + 3) * POI;
    float c0 = 0.f, c1 = 0.f, c2 = 0.f, c3 = 0.f;
#pragma unroll 4
    for (int p = p0; p < p0 + PC; ++p) {
        float ev = emb[p * EMB + e];
        c0 = fmaf(a0[p], ev, c0);
        c1 = fmaf(a1[p], ev, c1);
        c2 = fmaf(a2[p], ev, c2);
        c3 = fmaf(a3[p], ev, c3);
    }
    part[(ch * BATCH + b0 + 0) * EMB + e] = c0;
    part[(ch * BATCH + b0 + 1) * EMB + e] = c1;
    part[(ch * BATCH + b0 + 2) * EMB + e] = c2;
    part[(ch * BATCH + b0 + 3) * EMB + e] = c3;
}

// ---------------- ctx = sum of NCH partials ----------------
__global__ void ctx_reduce_kernel(const float* __restrict__ part,
                                  float* __restrict__ ctx) {
    int b = blockIdx.x;
    int e = threadIdx.x;               // 256
    float s = 0.f;
#pragma unroll
    for (int ch = 0; ch < NCH; ch++) s += part[(ch * BATCH + b) * EMB + e];
    ctx[b * EMB + e] = s;
}

// ---------------- launch ----------------
extern "C" void kernel_launch(void* const* d_in, const int* in_sizes, int n_in,
                              void* d_out, int out_size) {
    const int*   x          = (const int*)  d_in[0];
    const float* query      = (const float*)d_in[1];
    const float* emb        = (const float*)d_in[2];
    // d_in[3] = A_hat (unused)
    const float* dec_hidden = (const float*)d_in[4];
    const float* cat_dec    = (const float*)d_in[5];
    const float* gru_kernel = (const float*)d_in[6];
    const float* gru_rec    = (const float*)d_in[7];
    const float* gru_bias   = (const float*)d_in[8];
    const float* W1_w       = (const float*)d_in[9];
    const float* W1_b       = (const float*)d_in[10];
    const float* W2_w       = (const float*)d_in[11];
    const float* W2_b       = (const float*)d_in[12];
    const float* V_w        = (const float*)d_in[13];
    const float* V_b        = (const float*)d_in[14];
    const float* fc_w       = (const float*)d_in[15];
    const float* fc_b       = (const float*)d_in[16];

    float* out        = (float*)d_out;
    float* out_logits = out;
    float* out_state  = (out_size >= BATCH * POI + BATCH * UNITS)
                        ? out + BATCH * POI : nullptr;
    float* out_output = (out_size >= BATCH * POI + 2 * BATCH * UNITS)
                        ? out + BATCH * POI + BATCH * UNITS : nullptr;

    float *g_h_p, *g_qp_p, *g_ctx_p, *g_vp_p, *g_sc_p, *g_cp_p;
    float *g_grup_p, *g_qpp_p, *g_fcp_p;
    cudaGetSymbolAddress((void**)&g_h_p,    g_h);
    cudaGetSymbolAddress((void**)&g_qp_p,   g_qproj);
    cudaGetSymbolAddress((void**)&g_ctx_p,  g_ctx);
    cudaGetSymbolAddress((void**)&g_vp_p,   g_vproj);
    cudaGetSymbolAddress((void**)&g_sc_p,   g_score);
    cudaGetSymbolAddress((void**)&g_cp_p,   g_ctxpart);
    cudaGetSymbolAddress((void**)&g_grup_p, g_gru_part);
    cudaGetSymbolAddress((void**)&g_qpp_p,  g_qp_part);
    cudaGetSymbolAddress((void**)&g_fcp_p,  g_fc_part);

    // One-time stream/event setup (created on the uncaptured correctness call).
    static cudaStream_t s2 = nullptr, s3 = nullptr;
    static cudaEvent_t evFork = nullptr, evVP = nullptr, evH = nullptr, evFC = nullptr;
    if (!s2) {
        cudaStreamCreateWithFlags(&s2, cudaStreamNonBlocking);
        cudaStreamCreateWithFlags(&s3, cudaStreamNonBlocking);
        cudaEventCreateWithFlags(&evFork, cudaEventDisableTiming);
        cudaEventCreateWithFlags(&evVP, cudaEventDisableTiming);
        cudaEventCreateWithFlags(&evH, cudaEventDisableTiming);
        cudaEventCreateWithFlags(&evFC, cudaEventDisableTiming);
    }

    // ---- fork ----
    cudaEventRecord(evFork, 0);
    cudaStreamWaitEvent(s2, evFork, 0);
    cudaStreamWaitEvent(s3, evFork, 0);

    // s2: vproj = emb @ W1 + b (R8-proven 128x64 shape, single launch)
    gemm_v2_kernel<128, 64, 8, 4><<<dim3(UNITS / 64, (POI + 127) / 128, 1), 256, 0, s2>>>(
        emb, W1_w, W1_b, g_vp_p, POI, UNITS, EMB, EMB);
    cudaEventRecord(evVP, s2);

    // s3: fc cat_dec term (K rows 768..1279), slabs 0..3 — needs only inputs
    gemm_v2_kernel<64, 128, 4, 8><<<dim3((POI + 127) / 128, 1, 4), 256, 0, s3>>>(
        cat_dec, fc_w + (size_t)(EMB + UNITS) * POI, nullptr, g_fcp_p,
        BATCH, POI, UNITS, 128);

    // main: GRU chain
    gru_mm_kernel<<<dim3(3 * UNITS / 64, 1, 16), 256>>>(
        x, query, emb, dec_hidden, gru_kernel, gru_rec, g_grup_p);
    gru_gates_kernel<<<BATCH, UNITS>>>(g_grup_p, gru_bias, dec_hidden,
                                       g_h_p, out_state, out_output);
    cudaEventRecord(evH, 0);

    // s3: fc output_ term (K rows 256..767), slabs 4..7 — needs h
    cudaStreamWaitEvent(s3, evH, 0);
    gemm_v2_kernel<64, 128, 4, 8><<<dim3((POI + 127) / 128, 1, 4), 256, 0, s3>>>(
        g_h_p, fc_w + (size_t)EMB * POI, nullptr, g_fcp_p + (size_t)4 * BATCH * POI,
        BATCH, POI, UNITS, 128);
    cudaEventRecord(evFC, s3);

    // main: q_proj = h @ W2 + b (split 8)
    gemm_v2_kernel<64, 64, 4, 4><<<dim3(UNITS / 64, 1, 8), 256>>>(
        g_h_p, W2_w, nullptr, g_qpp_p, BATCH, UNITS, UNITS, 64);
    reduce_bias_kernel<<<(BATCH * UNITS + 255) / 256, 256>>>(
        g_qpp_p, W2_b, g_qp_p, BATCH * UNITS, UNITS, 8);

    // main: attention (waits on vproj)
    cudaStreamWaitEvent(0, evVP, 0);
    attn_score_kernel<<<dim3((POI + 127) / 128, BATCH / 4), 128>>>(
        g_vp_p, g_qp_p, V_w, V_b, g_sc_p);
    softmax_rows_kernel<<<BATCH, 256>>>(g_sc_p);
    context_partial_kernel<<<dim3(BATCH / 4, NCH), 256>>>(g_sc_p, emb, g_cp_p);
    ctx_reduce_kernel<<<BATCH, 256>>>(g_cp_p, g_ctx_p);

    // main: fc context term (K rows 0..255), slabs 8..9
    gemm_v2_kernel<64, 128, 4, 8><<<dim3((POI + 127) / 128, 1, 2), 256>>>(
        g_ctx_p, fc_w, nullptr, g_fcp_p + (size_t)8 * BATCH * POI,
        BATCH, POI, EMB, 128);

    // main: final reduce over 10 slabs + bias (waits on s3's fc terms)
    cudaStreamWaitEvent(0, evFC, 0);
    reduce_bias_kernel<<<(BATCH * POI + 255) / 256, 256>>>(
        g_fcp_p, fc_b, out_logits, BATCH * POI, POI, 10);
}

// round 12
// speedup vs baseline: 1.2086x; 1.0287x over previous
#include <cuda_runtime.h>
#include <cuda_bf16.h>
#include <math.h>
#include <cstdint>

#define POI   5000
#define EMB   256
#define UNITS 512
#define QDIM  256
#define BATCH 64
#define X1DIM  (EMB + QDIM)        // 512
#define NCH    10                  // context p-chunks (5000/10 = 500)

// ---------------- scratch (no cudaMalloc allowed; disjoint per concurrent use) --
__device__ float g_h[BATCH * UNITS];
__device__ float g_qproj[BATCH * UNITS];
__device__ float g_ctx[BATCH * EMB];
__device__ float g_vproj[POI * UNITS];                 // 10.24 MB
__device__ float g_score[BATCH * POI];
__device__ float g_ctxpart[NCH * BATCH * EMB];
__device__ float g_gru_part[16 * BATCH * 3 * UNITS];   // 6.3 MB
__device__ float g_qp_part[8 * BATCH * UNITS];         // 1.0 MB
__device__ float g_fc_part[10 * BATCH * POI];          // 12.8 MB
__device__ __nv_bfloat16 g_emb_bf[POI * EMB];          // 2.56 MB
__device__ __nv_bfloat16 g_w1t_bf[UNITS * EMB];        // 0.26 MB (W1 transposed)

__device__ __forceinline__ float tanh_ap(float x) {
    float y;
    asm("tanh.approx.f32 %0, %1;" : "=f"(y) : "f"(x));
    return y;
}

// ---------------- fp32 -> bf16 conversion (emb row-major, W1 transposed) --------
__global__ void convert_bf16_kernel(const float* __restrict__ emb,
                                    const float* __restrict__ W1,
                                    __nv_bfloat16* __restrict__ emb_bf,
                                    __nv_bfloat16* __restrict__ w1t_bf) {
    int idx = blockIdx.x * 256 + threadIdx.x;
    if (idx < POI * EMB) emb_bf[idx] = __float2bfloat16(emb[idx]);
    if (idx < UNITS * EMB) {
        int u = idx >> 8;          // /EMB
        int k = idx & 255;
        w1t_bf[idx] = __float2bfloat16(W1[k * UNITS + u]);
    }
}

// ---------------- vproj via HMMA (mma.sync m16n8k16 bf16) -----------------------
// D[128p x 64u] per CTA; 8 warps, each warp = 16 p-rows x 64 u-cols, K=256.
// A = emb_bf (row-major), B = w1t_bf (col-major: u row, k contiguous).
// grid (UNITS/64, ceil(POI/128)), block 256.
__global__ void __launch_bounds__(256)
vproj_hmma_kernel(const __nv_bfloat16* __restrict__ emb_bf,
                  const __nv_bfloat16* __restrict__ w1t_bf,
                  const float* __restrict__ W1_b,
                  float* __restrict__ vproj) {
    const int warp = threadIdx.x >> 5;
    const int lane = threadIdx.x & 31;
    const int grp = lane >> 2;         // 0..7
    const int qid = lane & 3;          // 0..3
    const int n0 = blockIdx.x * 64;
    const int m0 = blockIdx.y * 128 + warp * 16;

    const int row0 = m0 + grp;         // A rows for a0/a2, D rows for d0/d1
    const int row1 = m0 + grp + 8;     // A rows for a1/a3, D rows for d2/d3
    const bool v0 = row0 < POI;
    const bool v1 = row1 < POI;

    float d[8][4];
#pragma unroll
    for (int nt = 0; nt < 8; nt++)
#pragma unroll
        for (int j = 0; j < 4; j++) d[nt][j] = 0.f;

#pragma unroll 4
    for (int k0 = 0; k0 < EMB; k0 += 16) {
        // A fragment (row-major m16k16): 4 x b32 (2 bf16 each)
        uint32_t a0 = 0, a1 = 0, a2 = 0, a3 = 0;
        if (v0) {
            const uint32_t* pa = (const uint32_t*)(emb_bf + (size_t)row0 * EMB + k0 + qid * 2);
            a0 = pa[0];                // k = k0 + qid*2
            a2 = pa[4];                // k + 8
        }
        if (v1) {
            const uint32_t* pa = (const uint32_t*)(emb_bf + (size_t)row1 * EMB + k0 + qid * 2);
            a1 = pa[0];
            a3 = pa[4];
        }
#pragma unroll
        for (int nt = 0; nt < 8; nt++) {
            // B fragment (col-major k16n8): col u = n0 + nt*8 + grp, k = k0 + qid*2 (+8)
            const uint32_t* pb = (const uint32_t*)(w1t_bf + (size_t)(n0 + nt * 8 + grp) * EMB + k0 + qid * 2);
            uint32_t b0 = pb[0];
            uint32_t b1 = pb[4];
            asm volatile(
                "mma.sync.aligned.m16n8k16.row.col.f32.bf16.bf16.f32 "
                "{%0,%1,%2,%3}, {%4,%5,%6,%7}, {%8,%9}, {%0,%1,%2,%3};"
                : "+f"(d[nt][0]), "+f"(d[nt][1]), "+f"(d[nt][2]), "+f"(d[nt][3])
                : "r"(a0), "r"(a1), "r"(a2), "r"(a3), "r"(b0), "r"(b1));
        }
    }

    // D layout: d0/d1 -> (row0, n + 2*qid + {0,1}); d2/d3 -> (row1, same cols)
    if (v0) {
        float* dst = vproj + (size_t)row0 * UNITS;
#pragma unroll
        for (int nt = 0; nt < 8; nt++) {
            int n = n0 + nt * 8 + qid * 2;
            float2 v = make_float2(d[nt][0] + W1_b[n], d[nt][1] + W1_b[n + 1]);
            *(float2*)(dst + n) = v;
        }
    }
    if (v1) {
        float* dst = vproj + (size_t)row1 * UNITS;
#pragma unroll
        for (int nt = 0; nt < 8; nt++) {
            int n = n0 + nt * 8 + qid * 2;
            float2 v = make_float2(d[nt][2] + W1_b[n], d[nt][3] + W1_b[n + 1]);
            *(float2*)(dst + n) = v;
        }
    }
}

// ---------------- gemm_v2: C[M,N] = A[M,K] @ W[K,N] (+bias iff gridDim.z==1) -----
template <int BM, int BN, int TM, int TN>
__global__ void gemm_v2_kernel(const float* __restrict__ A,
                               const float* __restrict__ W,
                               const float* __restrict__ bias,
                               float* __restrict__ out,
                               int M, int N, int K, int kchunk) {
    __shared__ float As[32][BM + 1];
    __shared__ float Ws[32][BN];
    const int tid = threadIdx.x;
    const int r = tid >> 4;
    const int c = tid & 15;
    const int n0 = blockIdx.x * BN;
    const int m0 = blockIdx.y * BM;
    const int kbase = blockIdx.z * kchunk;

    float acc[TM][TN];
#pragma unroll
    for (int i = 0; i < TM; i++)
#pragma unroll
        for (int j = 0; j < TN; j++) acc[i][j] = 0.f;

    for (int kk = kbase; kk < kbase + kchunk; kk += 32) {
#pragma unroll
        for (int pass = 0; pass < (BM * 32) / 1024; pass++) {
            int idx = pass * 1024 + tid * 4;
            int m = idx >> 5;
            int k = idx & 31;
            float4 v = make_float4(0.f, 0.f, 0.f, 0.f);
            if (m0 + m < M) v = *(const float4*)(A + (size_t)(m0 + m) * K + kk + k);
            As[k + 0][m] = v.x;
            As[k + 1][m] = v.y;
            As[k + 2][m] = v.z;
            As[k + 3][m] = v.w;
        }
#pragma unroll
        for (int pass = 0; pass < (32 * BN) / 1024; pass++) {
            int idx = pass * 1024 + tid * 4;
            int k = idx / BN;
            int n = idx % BN;
            float4 v = make_float4(0.f, 0.f, 0.f, 0.f);
            if (n0 + n < N) v = *(const float4*)(W + (size_t)(kk + k) * N + n0 + n);
            *(float4*)&Ws[k][n] = v;
        }
        __syncthreads();
#pragma unroll
        for (int k = 0; k < 32; k++) {
            float a[TM];
#pragma unroll
            for (int i = 0; i < TM; i++) a[i] = As[k][r * TM + i];
            float b[TN];
#pragma unroll
            for (int j = 0; j < TN; j += 4)
                *(float4*)&b[j] = *(const float4*)&Ws[k][c * TN + j];
#pragma unroll
            for (int i = 0; i < TM; i++)
#pragma unroll
                for (int j = 0; j < TN; j++)
                    acc[i][j] = fmaf(a[i], b[j], acc[i][j]);
        }
        __syncthreads();
    }

    const bool direct = (gridDim.z == 1);
    float* dst = direct ? out : out + (size_t)blockIdx.z * M * N;
#pragma unroll
    for (int i = 0; i < TM; i++) {
        int m = m0 + r * TM + i;
        if (m >= M) continue;
#pragma unroll
        for (int j = 0; j < TN; j += 4) {
            int n = n0 + c * TN + j;
            if (n < N) {
                float4 v;
                v.x = acc[i][j + 0] + (direct ? bias[n + 0] : 0.f);
                v.y = acc[i][j + 1] + (direct ? bias[n + 1] : 0.f);
                v.z = acc[i][j + 2] + (direct ? bias[n + 2] : 0.f);
                v.w = acc[i][j + 3] + (direct ? bias[n + 3] : 0.f);
                *(float4*)(dst + (size_t)m * N + n) = v;
            }
        }
    }
}

// ---------------- merged GRU matmuls: slabs 0..7 = xm (x1 built inline), 8..15 = hm
__global__ void gru_mm_kernel(const int* __restrict__ x,
                              const float* __restrict__ query,
                              const float* __restrict__ emb,
                              const float* __restrict__ dec_hidden,
                              const float* __restrict__ Wk,
                              const float* __restrict__ Wr,
                              float* __restrict__ part) {
    const int NN = 3 * UNITS;
    __shared__ float As[32][65];
    __shared__ float Ws[32][64];
    const int tid = threadIdx.x;
    const int r = tid >> 4;
    const int c = tid & 15;
    const int n0 = blockIdx.x * 64;
    const bool isX = blockIdx.z < 8;
    const int kbase = (isX ? blockIdx.z : blockIdx.z - 8) * 64;
    const float* W = isX ? Wk : Wr;

    float acc[4][4];
#pragma unroll
    for (int i = 0; i < 4; i++)
#pragma unroll
        for (int j = 0; j < 4; j++) acc[i][j] = 0.f;

    for (int kk = kbase; kk < kbase + 64; kk += 32) {
#pragma unroll
        for (int pass = 0; pass < 2; pass++) {
            int idx = pass * 1024 + tid * 4;
            int m = idx >> 5;
            int k = idx & 31;
            int gk = kk + k;
            float4 v;
            if (isX) {
                if (gk < EMB)
                    v = *(const float4*)(emb + (size_t)x[m] * EMB + gk);
                else
                    v = *(const float4*)(query + (size_t)m * QDIM + gk - EMB);
            } else {
                v = *(const float4*)(dec_hidden + (size_t)m * UNITS + gk);
            }
            As[k + 0][m] = v.x;
            As[k + 1][m] = v.y;
            As[k + 2][m] = v.z;
            As[k + 3][m] = v.w;
        }
#pragma unroll
        for (int pass = 0; pass < 2; pass++) {
            int idx = pass * 1024 + tid * 4;
            int k = idx >> 6;
            int n = idx & 63;
            *(float4*)&Ws[k][n] = *(const float4*)(W + (size_t)(kk + k) * NN + n0 + n);
        }
        __syncthreads();
#pragma unroll
        for (int k = 0; k < 32; k++) {
            float a0 = As[k][r * 4 + 0];
            float a1 = As[k][r * 4 + 1];
            float a2 = As[k][r * 4 + 2];
            float a3 = As[k][r * 4 + 3];
            float4 b = *(const float4*)&Ws[k][c * 4];
            acc[0][0] = fmaf(a0, b.x, acc[0][0]); acc[0][1] = fmaf(a0, b.y, acc[0][1]);
            acc[0][2] = fmaf(a0, b.z, acc[0][2]); acc[0][3] = fmaf(a0, b.w, acc[0][3]);
            acc[1][0] = fmaf(a1, b.x, acc[1][0]); acc[1][1] = fmaf(a1, b.y, acc[1][1]);
            acc[1][2] = fmaf(a1, b.z, acc[1][2]); acc[1][3] = fmaf(a1, b.w, acc[1][3]);
            acc[2][0] = fmaf(a2, b.x, acc[2][0]); acc[2][1] = fmaf(a2, b.y, acc[2][1]);
            acc[2][2] = fmaf(a2, b.z, acc[2][2]); acc[2][3] = fmaf(a2, b.w, acc[2][3]);
            acc[3][0] = fmaf(a3, b.x, acc[3][0]); acc[3][1] = fmaf(a3, b.y, acc[3][1]);
            acc[3][2] = fmaf(a3, b.z, acc[3][2]); acc[3][3] = fmaf(a3, b.w, acc[3][3]);
        }
        __syncthreads();
    }

    float* dst = part + (size_t)blockIdx.z * BATCH * NN;
#pragma unroll
    for (int i = 0; i < 4; i++) {
        int m = r * 4 + i;
        int n = n0 + c * 4;
        float4 v = make_float4(acc[i][0], acc[i][1], acc[i][2], acc[i][3]);
        *(float4*)(dst + (size_t)m * NN + n) = v;
    }
}

// ---------------- reduce K-split partials + bias ----------------
__global__ void reduce_bias_kernel(const float* __restrict__ part,
                                   const float* __restrict__ bias,
                                   float* __restrict__ C,
                                   int MN, int N, int S) {
    int i = blockIdx.x * 256 + threadIdx.x;
    if (i >= MN) return;
    float s = 0.f;
    for (int z = 0; z < S; z++) s += part[(size_t)z * MN + i];
    C[i] = s + bias[i % N];
}

// ---------------- GRU gates: sums 8 xm slabs + 8 hm slabs + bias ----------------
__global__ void gru_gates_kernel(const float* __restrict__ part,
                                 const float* __restrict__ bias,
                                 const float* __restrict__ h_in,
                                 float* __restrict__ h_scratch,
                                 float* __restrict__ out_state,
                                 float* __restrict__ out_output) {
    const int NN = 3 * UNITS;
    int b = blockIdx.x;
    int u = threadIdx.x;               // 512
    float xz = bias[u], xr = bias[UNITS + u], xh = bias[2 * UNITS + u];
    float hz = bias[NN + u], hr = bias[NN + UNITS + u], hh = bias[NN + 2 * UNITS + u];
#pragma unroll
    for (int z = 0; z < 8; z++) {
        const float* px = part + (size_t)z * BATCH * NN + b * NN;
        const float* ph = part + (size_t)(8 + z) * BATCH * NN + b * NN;
        xz += px[u]; xr += px[UNITS + u]; xh += px[2 * UNITS + u];
        hz += ph[u]; hr += ph[UNITS + u]; hh += ph[2 * UNITS + u];
    }
    float z = 1.f / (1.f + expf(-(xz + hz)));
    float r = 1.f / (1.f + expf(-(xr + hr)));
    float hc = tanhf(xh + r * hh);
    float h = h_in[b * UNITS + u];
    float hn = z * h + (1.f - z) * hc;
    h_scratch[b * UNITS + u] = hn;
    if (out_state)  out_state[b * UNITS + u] = hn;
    if (out_output) out_output[b * UNITS + u] = hn;
}

// ---------------- attention score, 4 batch rows per block (proven) --------------
__global__ void attn_score_kernel(const float* __restrict__ vproj,
                                  const float* __restrict__ qproj,
                                  const float* __restrict__ Vw,
                                  const float* __restrict__ Vb,
                                  float* __restrict__ score) {
    __shared__ float q_s[4][UNITS];
    __shared__ float vw_s[UNITS];
    __shared__ float v_s[128][33];
    const int tid = threadIdx.x;       // 128
    const int p0 = blockIdx.x * 128;
    const int b0 = blockIdx.y * 4;

    for (int t = tid; t < 4 * UNITS; t += 128) {
        int b = t >> 9, u = t & 511;
        q_s[b][u] = qproj[(b0 + b) * UNITS + u];
    }
    for (int t = tid; t < UNITS; t += 128) vw_s[t] = Vw[t];

    float acc0 = 0.f, acc1 = 0.f, acc2 = 0.f, acc3 = 0.f;
    for (int u0 = 0; u0 < UNITS; u0 += 32) {
        __syncthreads();
        for (int t = tid; t < 128 * 32; t += 128) {
            int p = t >> 5, j = t & 31;
            v_s[p][j] = (p0 + p < POI) ? vproj[(size_t)(p0 + p) * UNITS + u0 + j] : 0.f;
        }
        __syncthreads();
#pragma unroll
        for (int j = 0; j < 32; ++j) {
            float v  = v_s[tid][j];
            float vw = vw_s[u0 + j];
            acc0 = fmaf(vw, tanh_ap(v + q_s[0][u0 + j]), acc0);
            acc1 = fmaf(vw, tanh_ap(v + q_s[1][u0 + j]), acc1);
            acc2 = fmaf(vw, tanh_ap(v + q_s[2][u0 + j]), acc2);
            acc3 = fmaf(vw, tanh_ap(v + q_s[3][u0 + j]), acc3);
        }
    }
    if (p0 + tid < POI) {
        float vb = Vb[0];
        score[(size_t)(b0 + 0) * POI + p0 + tid] = acc0 + vb;
        score[(size_t)(b0 + 1) * POI + p0 + tid] = acc1 + vb;
        score[(size_t)(b0 + 2) * POI + p0 + tid] = acc2 + vb;
        score[(size_t)(b0 + 3) * POI + p0 + tid] = acc3 + vb;
    }
}

// ---------------- softmax over POI per batch row (in place) ----------------
__global__ void softmax_rows_kernel(float* __restrict__ score) {
    int b = blockIdx.x;
    int tid = threadIdx.x;             // 256
    __shared__ float red[256];
    float m = -1e30f;
    for (int p = tid; p < POI; p += 256) m = fmaxf(m, score[b * POI + p]);
    red[tid] = m;
    __syncthreads();
    for (int s = 128; s > 0; s >>= 1) {
        if (tid < s) red[tid] = fmaxf(red[tid], red[tid + s]);
        __syncthreads();
    }
    m = red[0];
    __syncthreads();
    float sum = 0.f;
    for (int p = tid; p < POI; p += 256) {
        float e = __expf(score[b * POI + p] - m);
        score[b * POI + p] = e;
        sum += e;
    }
    red[tid] = sum;
    __syncthreads();
    for (int s = 128; s > 0; s >>= 1) {
        if (tid < s) red[tid] += red[tid + s];
        __syncthreads();
    }
    float inv = 1.f / red[0];
    for (int p = tid; p < POI; p += 256) score[b * POI + p] *= inv;
}

// ---------------- context partials: 4 batch rows per block, NCH p-chunks --------
__global__ void context_partial_kernel(const float* __restrict__ attn,
                                       const float* __restrict__ emb,
                                       float* __restrict__ part) {
    const int PC = POI / NCH;          // 500
    int b0 = blockIdx.x * 4;
    int ch = blockIdx.y;
    int e  = threadIdx.x;              // 256 == EMB
    int p0 = ch * PC;
    const float* a0 = attn + (b0 + 0) * POI;
    const float* a1 = attn + (b0 + 1) * POI;
    const float* a2 = attn + (b0 + 2) * POI;
    const float* a3 = attn + (b0 + 3) * POI;
    float c0 = 0.f, c1 = 0.f, c2 = 0.f, c3 = 0.f;
#pragma unroll 4
    for (int p = p0; p < p0 + PC; ++p) {
        float ev = emb[p * EMB + e];
        c0 = fmaf(a0[p], ev, c0);
        c1 = fmaf(a1[p], ev, c1);
        c2 = fmaf(a2[p], ev, c2);
        c3 = fmaf(a3[p], ev, c3);
    }
    part[(ch * BATCH + b0 + 0) * EMB + e] = c0;
    part[(ch * BATCH + b0 + 1) * EMB + e] = c1;
    part[(ch * BATCH + b0 + 2) * EMB + e] = c2;
    part[(ch * BATCH + b0 + 3) * EMB + e] = c3;
}

// ---------------- ctx = sum of NCH partials ----------------
__global__ void ctx_reduce_kernel(const float* __restrict__ part,
                                  float* __restrict__ ctx) {
    int b = blockIdx.x;
    int e = threadIdx.x;               // 256
    float s = 0.f;
#pragma unroll
    for (int ch = 0; ch < NCH; ch++) s += part[(ch * BATCH + b) * EMB + e];
    ctx[b * EMB + e] = s;
}

// ---------------- launch ----------------
extern "C" void kernel_launch(void* const* d_in, const int* in_sizes, int n_in,
                              void* d_out, int out_size) {
    const int*   x          = (const int*)  d_in[0];
    const float* query      = (const float*)d_in[1];
    const float* emb        = (const float*)d_in[2];
    // d_in[3] = A_hat (unused)
    const float* dec_hidden = (const float*)d_in[4];
    const float* cat_dec    = (const float*)d_in[5];
    const float* gru_kernel = (const float*)d_in[6];
    const float* gru_rec    = (const float*)d_in[7];
    const float* gru_bias   = (const float*)d_in[8];
    const float* W1_w       = (const float*)d_in[9];
    const float* W1_b       = (const float*)d_in[10];
    const float* W2_w       = (const float*)d_in[11];
    const float* W2_b       = (const float*)d_in[12];
    const float* V_w        = (const float*)d_in[13];
    const float* V_b        = (const float*)d_in[14];
    const float* fc_w       = (const float*)d_in[15];
    const float* fc_b       = (const float*)d_in[16];

    float* out        = (float*)d_out;
    float* out_logits = out;
    float* out_state  = (out_size >= BATCH * POI + BATCH * UNITS)
                        ? out + BATCH * POI : nullptr;
    float* out_output = (out_size >= BATCH * POI + 2 * BATCH * UNITS)
                        ? out + BATCH * POI + BATCH * UNITS : nullptr;

    float *g_h_p, *g_qp_p, *g_ctx_p, *g_vp_p, *g_sc_p, *g_cp_p;
    float *g_grup_p, *g_qpp_p, *g_fcp_p;
    __nv_bfloat16 *g_embbf_p, *g_w1tbf_p;
    cudaGetSymbolAddress((void**)&g_h_p,     g_h);
    cudaGetSymbolAddress((void**)&g_qp_p,    g_qproj);
    cudaGetSymbolAddress((void**)&g_ctx_p,   g_ctx);
    cudaGetSymbolAddress((void**)&g_vp_p,    g_vproj);
    cudaGetSymbolAddress((void**)&g_sc_p,    g_score);
    cudaGetSymbolAddress((void**)&g_cp_p,    g_ctxpart);
    cudaGetSymbolAddress((void**)&g_grup_p,  g_gru_part);
    cudaGetSymbolAddress((void**)&g_qpp_p,   g_qp_part);
    cudaGetSymbolAddress((void**)&g_fcp_p,   g_fc_part);
    cudaGetSymbolAddress((void**)&g_embbf_p, g_emb_bf);
    cudaGetSymbolAddress((void**)&g_w1tbf_p, g_w1t_bf);

    // One-time stream/event setup (on the uncaptured correctness call).
    static cudaStream_t s2 = nullptr, s3 = nullptr;
    static cudaEvent_t evFork = nullptr, evVP = nullptr, evH = nullptr, evFC = nullptr;
    if (!s2) {
        cudaStreamCreateWithFlags(&s2, cudaStreamNonBlocking);
        cudaStreamCreateWithFlags(&s3, cudaStreamNonBlocking);
        cudaEventCreateWithFlags(&evFork, cudaEventDisableTiming);
        cudaEventCreateWithFlags(&evVP, cudaEventDisableTiming);
        cudaEventCreateWithFlags(&evH, cudaEventDisableTiming);
        cudaEventCreateWithFlags(&evFC, cudaEventDisableTiming);
    }

    // ---- fork ----
    cudaEventRecord(evFork, 0);
    cudaStreamWaitEvent(s2, evFork, 0);
    cudaStreamWaitEvent(s3, evFork, 0);

    // s2: bf16 convert, then vproj via HMMA tensor cores (320 CTAs)
    convert_bf16_kernel<<<(POI * EMB + 255) / 256, 256, 0, s2>>>(
        emb, W1_w, g_embbf_p, g_w1tbf_p);
    vproj_hmma_kernel<<<dim3(UNITS / 64, (POI + 127) / 128), 256, 0, s2>>>(
        g_embbf_p, g_w1tbf_p, W1_b, g_vp_p);
    cudaEventRecord(evVP, s2);

    // s3: fc cat_dec term (K rows 768..1279), slabs 0..3 — needs only inputs
    gemm_v2_kernel<64, 128, 4, 8><<<dim3((POI + 127) / 128, 1, 4), 256, 0, s3>>>(
        cat_dec, fc_w + (size_t)(EMB + UNITS) * POI, nullptr, g_fcp_p,
        BATCH, POI, UNITS, 128);

    // main: GRU chain
    gru_mm_kernel<<<dim3(3 * UNITS / 64, 1, 16), 256>>>(
        x, query, emb, dec_hidden, gru_kernel, gru_rec, g_grup_p);
    gru_gates_kernel<<<BATCH, UNITS>>>(g_grup_p, gru_bias, dec_hidden,
                                       g_h_p, out_state, out_output);
    cudaEventRecord(evH, 0);

    // s3: fc output_ term (K rows 256..767), slabs 4..7 — needs h
    cudaStreamWaitEvent(s3, evH, 0);
    gemm_v2_kernel<64, 128, 4, 8><<<dim3((POI + 127) / 128, 1, 4), 256, 0, s3>>>(
        g_h_p, fc_w + (size_t)EMB * POI, nullptr, g_fcp_p + (size_t)4 * BATCH * POI,
        BATCH, POI, UNITS, 128);
    cudaEventRecord(evFC, s3);

    // main: q_proj = h @ W2 + b (split 8)
    gemm_v2_kernel<64, 64, 4, 4><<<dim3(UNITS / 64, 1, 8), 256>>>(
        g_h_p, W2_w, nullptr, g_qpp_p, BATCH, UNITS, UNITS, 64);
    reduce_bias_kernel<<<(BATCH * UNITS + 255) / 256, 256>>>(
        g_qpp_p, W2_b, g_qp_p, BATCH * UNITS, UNITS, 8);

    // main: attention (waits on vproj)
    cudaStreamWaitEvent(0, evVP, 0);
    attn_score_kernel<<<dim3((POI + 127) / 128, BATCH / 4), 128>>>(
        g_vp_p, g_qp_p, V_w, V_b, g_sc_p);
    softmax_rows_kernel<<<BATCH, 256>>>(g_sc_p);
    context_partial_kernel<<<dim3(BATCH / 4, NCH), 256>>>(g_sc_p, emb, g_cp_p);
    ctx_reduce_kernel<<<BATCH, 256>>>(g_cp_p, g_ctx_p);

    // main: fc context term (K rows 0..255), slabs 8..9
    gemm_v2_kernel<64, 128, 4, 8><<<dim3((POI + 127) / 128, 1, 2), 256>>>(
        g_ctx_p, fc_w, nullptr, g_fcp_p + (size_t)8 * BATCH * POI,
        BATCH, POI, EMB, 128);

    // main: final reduce over 10 slabs + bias (waits on s3's fc terms)
    cudaStreamWaitEvent(0, evFC, 0);
    reduce_bias_kernel<<<(BATCH * POI + 255) / 256, 256>>>(
        g_fcp_p, fc_b, out_logits, BATCH * POI, POI, 10);
}